// round 14
// baseline (speedup 1.0000x reference)
#include <cuda_runtime.h>
#include <math.h>
#include <stdint.h>

#define BB 4
#define CC 128
#define NBOX 4
#define BTC 32
#define HH 256
#define WW 256
#define HWSZ (HH*WW)
#define SW 257                      // integral image row stride

// scratch (static device globals; no dynamic allocation)
__device__ float g_z[BB*BTC*HH*WW];       // ROW-SCANNED z = rowcumsum(BN1(conv))
__device__ float g_S[BB*BTC*SW*SW];       // 2D integral image, zero borders
__device__ float g_ctot[BB*BTC][4][WW];   // per-chunk column totals

__device__ __forceinline__ uint32_t packbf(float hi, float lo) {
    uint32_t r;
    asm("cvt.rn.bf16x2.f32 %0, %1, %2;" : "=r"(r) : "f"(hi), "f"(lo));
    return r;
}
__device__ __forceinline__ void mma_bf16(float d[4], const uint32_t a[4],
                                         uint32_t b0, uint32_t b1) {
    asm volatile(
        "mma.sync.aligned.m16n8k16.row.col.f32.bf16.bf16.f32 "
        "{%0,%1,%2,%3}, {%4,%5,%6,%7}, {%8,%9}, {%0,%1,%2,%3};\n"
        : "+f"(d[0]), "+f"(d[1]), "+f"(d[2]), "+f"(d[3])
        : "r"(a[0]), "r"(a[1]), "r"(a[2]), "r"(a[3]), "r"(b0), "r"(b1));
}
__device__ __forceinline__ uint32_t smem_u32(const void* p) {
    uint32_t a;
    asm("{ .reg .u64 t; cvta.to.shared.u64 t, %1; cvt.u32.u64 %0, t; }"
        : "=r"(a) : "l"(p));
    return a;
}
__device__ __forceinline__ void cp16(uint32_t dst, const float* src) {
    asm volatile("cp.async.ca.shared.global [%0], [%1], 16;\n"
                 :: "r"(dst), "l"(src));
}

// dynamic smem layout for k1 (bytes)
#define SM_SINV  0         // 32 f
#define SM_SBIAS 128       // 32 f
#define SM_WTOT  256       // [8][8] f
#define SM_WS    512       // wstb[64][40] u32 bf16x2 weight pairs (10240 B)
#define SM_XS    10752     // xs[2][16][268] f (34304 B); zs[32][260] aliases it
#define SM_TOTAL 45056

// ---------------------------------------------------------------------------
// Kernel 1: z = rowcumsum( BN1(x @ w1^T) ) via mma.sync bf16 m16n8k16,
// cp.async double-buffered 16-channel chunks (one k16 step per chunk).
// (known-good from round 13)
// ---------------------------------------------------------------------------
__global__ __launch_bounds__(256) void k1_mma_rowscan(
    const float* __restrict__ x, const float* __restrict__ w1,
    const float* __restrict__ g1, const float* __restrict__ b1,
    const float* __restrict__ m1, const float* __restrict__ v1)
{
    extern __shared__ char dsm[];
    float*    sinv  = (float*)(dsm + SM_SINV);
    float*    sbias = (float*)(dsm + SM_SBIAS);
    float*    wtot  = (float*)(dsm + SM_WTOT);
    uint32_t* wstb  = (uint32_t*)(dsm + SM_WS);   // [64][40] bf16x2 k-pairs
    float*    xs    = (float*)(dsm + SM_XS);      // [2][16][268]
    float*    zs    = (float*)(dsm + SM_XS);      // [32][260] alias (epilogue)

    const int tid  = threadIdx.x;
    const int w    = tid >> 5;
    const int lane = tid & 31;
    const int g    = lane >> 2;     // group id 0..7
    const int t    = lane & 3;      // thread-in-group 0..3

    const int pixbase = blockIdx.x * 256;
    const int b  = pixbase >> 16;
    const int ij = pixbase & 65535;

    if (tid < 32) {
        float inv = g1[tid] * rsqrtf(v1[tid] + 1e-5f);
        sinv[tid]  = inv;
        sbias[tid] = b1[tid] - m1[tid]*inv;
    }
    __syncthreads();

    // stage B = w1 * inv as bf16x2 pairs along k: wstb[c2][ch] = {w[2c2+1],w[2c2]}
    for (int idx = tid; idx < 64*BTC; idx += 256) {
        int c2 = idx >> 5;
        int ch = idx & 31;
        float inv = sinv[ch];
        wstb[c2*40 + ch] = packbf(w1[ch*CC + 2*c2 + 1] * inv,
                                  w1[ch*CC + 2*c2]     * inv);
    }
    __syncthreads();

    float acc[2][4][4];
    #pragma unroll
    for (int mt = 0; mt < 2; mt++)
        #pragma unroll
        for (int nt = 0; nt < 4; nt++)
            #pragma unroll
            for (int e = 0; e < 4; e++) acc[mt][nt][e] = 0.f;

    const int cl = tid >> 6;          // staging channel lane 0..3
    const int p4 = (tid & 63) * 4;    // staging pixel offset
    const float* xb = x + (size_t)b*CC*HWSZ + ij;
    const uint32_t xs_sb = smem_u32(xs);
    const int mypx0 = w*32 + g;       // fragment pixel base (mt adds 16)

    // prefetch chunk 0 into buf 0
    #pragma unroll
    for (int it = 0; it < 4; it++) {
        int c = it*4 + cl;            // local channel 0..15
        cp16(xs_sb + (uint32_t)(c*268 + p4)*4u,
             xb + (size_t)c*HWSZ + p4);
    }
    asm volatile("cp.async.commit_group;\n" ::);

    #pragma unroll
    for (int ch16 = 0; ch16 < 8; ch16++) {
        const int buf = ch16 & 1;
        if (ch16 < 7) {
            const int nb_ = ch16 + 1;
            const uint32_t bofs = (uint32_t)((nb_ & 1) * 16 * 268) * 4u;
            #pragma unroll
            for (int it = 0; it < 4; it++) {
                int c = it*4 + cl;
                cp16(xs_sb + bofs + (uint32_t)(c*268 + p4)*4u,
                     xb + (size_t)(nb_*16 + c)*HWSZ + p4);
            }
            asm volatile("cp.async.commit_group;\n" ::);
            asm volatile("cp.async.wait_group 1;\n" ::);
        } else {
            asm volatile("cp.async.wait_group 0;\n" ::);
        }
        __syncthreads();

        const float* xc = xs + buf*16*268;
        // ---- one k16 MMA step over this chunk ----
        uint32_t a[2][4];
        #pragma unroll
        for (int mt = 0; mt < 2; mt++) {
            const int px = mypx0 + mt*16;
            const float* r0 = xc + (2*t)*268;       // ch 2t
            const float* r1 = xc + (2*t+1)*268;     // ch 2t+1
            const float* r8 = xc + (2*t+8)*268;     // ch 2t+8
            const float* r9 = xc + (2*t+9)*268;     // ch 2t+9
            a[mt][0] = packbf(r1[px],     r0[px]);
            a[mt][1] = packbf(r1[px + 8], r0[px + 8]);
            a[mt][2] = packbf(r9[px],     r8[px]);
            a[mt][3] = packbf(r9[px + 8], r8[px + 8]);
        }
        const int kg2 = ch16*8;
        #pragma unroll
        for (int nt = 0; nt < 4; nt++) {
            uint32_t b0 = wstb[(kg2 + t)*40     + nt*8 + g];
            uint32_t b1 = wstb[(kg2 + t + 4)*40 + nt*8 + g];
            mma_bf16(acc[0][nt], a[0], b0, b1);
            mma_bf16(acc[1][nt], a[1], b0, b1);
        }
        __syncthreads();    // done reading buf before it is overwritten
    }

    // ---- scatter acc to zs[ch][260] (conflict-free, float4-aligned rows) ----
    #pragma unroll
    for (int mt = 0; mt < 2; mt++) {
        const int px = w*32 + mt*16 + g;
        #pragma unroll
        for (int nt = 0; nt < 4; nt++) {
            const int ch = nt*8 + 2*t;
            zs[ch*260 + px]           = acc[mt][nt][0];
            zs[(ch+1)*260 + px]       = acc[mt][nt][1];
            zs[ch*260 + px + 8]       = acc[mt][nt][2];
            zs[(ch+1)*260 + px + 8]   = acc[mt][nt][3];
        }
    }
    __syncthreads();

    // ---- bias + per-channel inclusive row scan (proven pattern) ----
    const int tp  = tid & 63;       // pixel group (4 px)
    const int tk  = tid >> 6;       // channel group (8 ch)
    const int wid = tid >> 5;

    float sc[4][8];
    float tot[8];
    #pragma unroll
    for (int q = 0; q < 8; q++) {
        const int ch = tk*8 + q;
        float4 v = *(float4*)&zs[ch*260 + tp*4];
        float bias = sbias[ch];
        float a0 = v.x + bias, a1 = v.y + bias, a2 = v.z + bias, a3 = v.w + bias;
        sc[0][q] = a0;
        sc[1][q] = sc[0][q] + a1;
        sc[2][q] = sc[1][q] + a2;
        sc[3][q] = sc[2][q] + a3;
        float s = sc[3][q];
        #pragma unroll
        for (int o = 1; o < 32; o <<= 1) {
            float u = __shfl_up_sync(0xffffffffu, s, o);
            if (lane >= o) s += u;
        }
        tot[q] = s;
        if (lane == 31) wtot[wid*8 + q] = s;
    }
    __syncthreads();

    #pragma unroll
    for (int q = 0; q < 8; q++) {
        const int ch = tk*8 + q;
        float off = tot[q] - sc[3][q];            // exclusive within warp
        if (wid & 1) off += wtot[(wid - 1)*8 + q];
        float4 r = make_float4(sc[0][q] + off, sc[1][q] + off,
                               sc[2][q] + off, sc[3][q] + off);
        *(float4*)(g_z + (size_t)(b*BTC + ch)*HWSZ + ij + tp*4) = r;
    }
}

// ---------------------------------------------------------------------------
// Kernel 2pre: per-chunk column totals of row-scanned z.
// ---------------------------------------------------------------------------
__global__ __launch_bounds__(256) void k2pre_chunktot()
{
    const int chunk = blockIdx.x;
    const int plane = blockIdx.y;
    const int j     = threadIdx.x;
    const float* zp = g_z + (size_t)plane*HWSZ + (size_t)(chunk*64)*WW + j;

    float acc = 0.f;
    #pragma unroll 8
    for (int r = 0; r < 64; r++)
        acc += zp[(size_t)r*WW];
    g_ctot[plane][chunk][j] = acc;
}

// ---------------------------------------------------------------------------
// Kernel 2a: chunk column cumsum seeded with earlier-chunk prefix -> FINAL S.
// ---------------------------------------------------------------------------
__global__ __launch_bounds__(256) void k2a_colsum_chunk()
{
    const int chunk = blockIdx.x;
    const int plane = blockIdx.y;
    const int j     = threadIdx.x;
    const int r0    = chunk * 64;

    const float* zp = g_z + (size_t)plane*HWSZ + (size_t)r0*WW + j;
    float* Sp = g_S + (size_t)plane*SW*SW;

    if (chunk == 0) {
        Sp[j] = 0.f;
        if (j == 0) Sp[256] = 0.f;
    }
    if (j < 64)
        Sp[(size_t)(r0 + j + 1)*SW] = 0.f;

    float acc = 0.f;
    for (int p = 0; p < chunk; p++)
        acc += g_ctot[plane][p][j];

    #pragma unroll 8
    for (int r = 0; r < 64; r++) {
        acc += zp[(size_t)r*WW];
        Sp[(size_t)(r0 + r + 1)*SW + (j + 1)] = acc;
    }
}

// ---------------------------------------------------------------------------
// Kernel 3: separable box filter; 16-row chunks with ROLLING vertical taps.
// Per thread: 34 S loads / 16 rows (vs 40), phase-2 4 LDS/px, inv_area folded.
// ---------------------------------------------------------------------------
__global__ __launch_bounds__(256) void k3_box(
    const float* __restrict__ x,
    const float* __restrict__ xmn_, const float* __restrict__ xmx_,
    const float* __restrict__ ymn_, const float* __restrict__ ymx_,
    const float* __restrict__ g2, const float* __restrict__ b2,
    const float* __restrict__ m2, const float* __restrict__ v2,
    float* __restrict__ out)
{
    __shared__ float Dv[16][SW];      // 16.4 KB

    const int bid = blockIdx.x;
    const int rc  = bid & 15;                 // 16-row chunk
    const int nb  = (bid >> 4) & (NBOX-1);
    const int bt  = (bid >> 6) & (BTC-1);
    const int b   = bid >> 11;
    const int j   = threadIdx.x;
    const int k   = bt*NBOX + nb;
    const int boxi = bt*NBOX + nb;

    const float xmn = xmn_[boxi], xmx = xmx_[boxi];
    const float ymn = ymn_[boxi], ymx = ymx_[boxi];
    const float inv_area = 1.f / ((xmx - xmn) * (ymx - ymn));

    const float* Sp = g_S + (size_t)(b*BTC + bt)*SW*SW;

    const int i0 = rc*16;
    const float aA = (float)i0 + xmx;          // raw (unclamped) anchors
    const float aB = (float)i0 + xmn;
    const float fAf = floorf(aA), fBf = floorf(aB);
    const int   rA0 = (int)fAf,  rB0 = (int)fBf;
    const float wA = aA - fAf,   wB = aB - fBf;

    // ---- phase 1: rolling 5-tap window over 4 groups of 4 rows ----
    {
        float SA[5], SB[5];
        #pragma unroll
        for (int tt = 0; tt < 5; tt++) {
            int ra = rA0 + tt;  ra = (ra > 256) ? 256 : ra;
            int rb = rB0 + tt;  rb = (rb > 256) ? 256 : rb;
            SA[tt] = (ra < 0) ? 0.f : Sp[(size_t)ra*SW + j];
            SB[tt] = (rb < 0) ? 0.f : Sp[(size_t)rb*SW + j];
        }
        #pragma unroll
        for (int q = 0; q < 4; q++) {
            if (q > 0) {
                SA[0] = SA[4];  SB[0] = SB[4];
                #pragma unroll
                for (int tt = 1; tt < 5; tt++) {
                    int ra = rA0 + 4*q + tt;  ra = (ra > 256) ? 256 : ra;
                    int rb = rB0 + 4*q + tt;  rb = (rb > 256) ? 256 : rb;
                    SA[tt] = (ra < 0) ? 0.f : Sp[(size_t)ra*SW + j];
                    SB[tt] = (rb < 0) ? 0.f : Sp[(size_t)rb*SW + j];
                }
            }
            #pragma unroll
            for (int tt = 0; tt < 4; tt++)
                Dv[4*q + tt][j] = (SA[tt]*(1.f-wA) + SA[tt+1]*wA)
                                - (SB[tt]*(1.f-wB) + SB[tt+1]*wB);
        }
    }
    if (j == 255) {   // column 256
        float TA[5], TB[5];
        #pragma unroll
        for (int tt = 0; tt < 5; tt++) {
            int ra = rA0 + tt;  ra = (ra > 256) ? 256 : ra;
            int rb = rB0 + tt;  rb = (rb > 256) ? 256 : rb;
            TA[tt] = (ra < 0) ? 0.f : Sp[(size_t)ra*SW + 256];
            TB[tt] = (rb < 0) ? 0.f : Sp[(size_t)rb*SW + 256];
        }
        #pragma unroll
        for (int q = 0; q < 4; q++) {
            if (q > 0) {
                TA[0] = TA[4];  TB[0] = TB[4];
                #pragma unroll
                for (int tt = 1; tt < 5; tt++) {
                    int ra = rA0 + 4*q + tt;  ra = (ra > 256) ? 256 : ra;
                    int rb = rB0 + 4*q + tt;  rb = (rb > 256) ? 256 : rb;
                    TA[tt] = (ra < 0) ? 0.f : Sp[(size_t)ra*SW + 256];
                    TB[tt] = (rb < 0) ? 0.f : Sp[(size_t)rb*SW + 256];
                }
            }
            #pragma unroll
            for (int tt = 0; tt < 4; tt++)
                Dv[4*q + tt][256] = (TA[tt]*(1.f-wA) + TA[tt+1]*wA)
                                  - (TB[tt]*(1.f-wB) + TB[tt+1]*wB);
        }
    }
    __syncthreads();

    // ---- phase 2: horizontal fractional box from smem ----
    float vA = fminf(fmaxf((float)j + ymx, 0.f), 256.f);
    float vB = fminf(fmaxf((float)j + ymn, 0.f), 256.f);
    float gA = fminf(floorf(vA), 255.f);
    float gB = fminf(floorf(vB), 255.f);
    int   jA = (int)gA, jB = (int)gB;
    float wvA = vA - gA, wvB = vB - gB;

    float inv2  = g2[k] * rsqrtf(v2[k] + 1e-3f);
    float bias2 = b2[k] - m2[k]*inv2;
    float c1    = inv_area * inv2;            // fold /area into BN2 scale

    const float* xrow = x   + ((size_t)(b*CC + k)*HH + i0)*WW + j;
    float*       orow = out + ((size_t)(b*CC + k)*HH + i0)*WW + j;

    #pragma unroll
    for (int r = 0; r < 16; r++) {
        float DA = Dv[r][jA]*(1.f - wvA) + Dv[r][jA+1]*wvA;
        float DB = Dv[r][jB]*(1.f - wvB) + Dv[r][jB+1]*wvB;
        float val = (DA - DB) * c1 + bias2;

        val = fmaxf(val, 0.f);
        orow[(size_t)r*WW] = fmaxf(xrow[(size_t)r*WW] + val, 0.f);
    }
}

// ---------------------------------------------------------------------------
extern "C" void kernel_launch(void* const* d_in, const int* in_sizes, int n_in,
                              void* d_out, int out_size)
{
    const float* x    = (const float*)d_in[0];
    const float* w1   = (const float*)d_in[1];
    const float* g1   = (const float*)d_in[2];
    const float* b1   = (const float*)d_in[3];
    const float* m1   = (const float*)d_in[4];
    const float* v1   = (const float*)d_in[5];
    const float* xmn  = (const float*)d_in[6];
    const float* xmx  = (const float*)d_in[7];
    const float* ymn  = (const float*)d_in[8];
    const float* ymx  = (const float*)d_in[9];
    const float* g2   = (const float*)d_in[10];
    const float* b2   = (const float*)d_in[11];
    const float* m2   = (const float*)d_in[12];
    const float* v2   = (const float*)d_in[13];
    float* out = (float*)d_out;

    cudaFuncSetAttribute(k1_mma_rowscan,
                         cudaFuncAttributeMaxDynamicSharedMemorySize, SM_TOTAL);

    k1_mma_rowscan<<<(BB*HWSZ)/256, 256, SM_TOTAL>>>(x, w1, g1, b1, m1, v1);
    k2pre_chunktot<<<dim3(4, BB*BTC), 256>>>();
    k2a_colsum_chunk<<<dim3(4, BB*BTC), 256>>>();
    k3_box<<<BB*BTC*NBOX*(HH/16), 256>>>(x, xmn, xmx, ymn, ymx, g2, b2, m2, v2, out);
}

// round 15
// speedup vs baseline: 1.3989x; 1.3989x over previous
#include <cuda_runtime.h>
#include <math.h>
#include <stdint.h>

#define BB 4
#define CC 128
#define NBOX 4
#define BTC 32
#define HH 256
#define WW 256
#define HWSZ (HH*WW)
#define SW 257                      // integral image row stride

// scratch (static device globals; no dynamic allocation)
__device__ float g_z[BB*BTC*HH*WW];       // ROW-SCANNED z = rowcumsum(BN1(conv))
__device__ float g_S[BB*BTC*SW*SW];       // 2D integral image, zero borders
__device__ float g_ctot[BB*BTC][8][WW];   // per-chunk (32-row) column totals

__device__ __forceinline__ uint32_t packbf(float hi, float lo) {
    uint32_t r;
    asm("cvt.rn.bf16x2.f32 %0, %1, %2;" : "=r"(r) : "f"(hi), "f"(lo));
    return r;
}
__device__ __forceinline__ void mma_bf16(float d[4], const uint32_t a[4],
                                         uint32_t b0, uint32_t b1) {
    asm volatile(
        "mma.sync.aligned.m16n8k16.row.col.f32.bf16.bf16.f32 "
        "{%0,%1,%2,%3}, {%4,%5,%6,%7}, {%8,%9}, {%0,%1,%2,%3};\n"
        : "+f"(d[0]), "+f"(d[1]), "+f"(d[2]), "+f"(d[3])
        : "r"(a[0]), "r"(a[1]), "r"(a[2]), "r"(a[3]), "r"(b0), "r"(b1));
}
__device__ __forceinline__ uint32_t smem_u32(const void* p) {
    uint32_t a;
    asm("{ .reg .u64 t; cvta.to.shared.u64 t, %1; cvt.u32.u64 %0, t; }"
        : "=r"(a) : "l"(p));
    return a;
}
__device__ __forceinline__ void cp16(uint32_t dst, const float* src) {
    asm volatile("cp.async.ca.shared.global [%0], [%1], 16;\n"
                 :: "r"(dst), "l"(src));
}

// dynamic smem layout for k1 (bytes)
#define SM_SINV  0         // 32 f
#define SM_SBIAS 128       // 32 f
#define SM_WTOT  256       // [8][8] f
#define SM_WS    512       // wstb[64][40] u32 bf16x2 weight pairs (10240 B)
#define SM_XS    10752     // xs[2][16][268] f (34304 B); zs[32][260] aliases it
#define SM_TOTAL 45056

// ---------------------------------------------------------------------------
// Kernel 1: z = rowcumsum( BN1(x @ w1^T) ) via mma.sync bf16 m16n8k16,
// cp.async double-buffered 16-channel chunks (known-good from round 13).
// ---------------------------------------------------------------------------
__global__ __launch_bounds__(256) void k1_mma_rowscan(
    const float* __restrict__ x, const float* __restrict__ w1,
    const float* __restrict__ g1, const float* __restrict__ b1,
    const float* __restrict__ m1, const float* __restrict__ v1)
{
    extern __shared__ char dsm[];
    float*    sinv  = (float*)(dsm + SM_SINV);
    float*    sbias = (float*)(dsm + SM_SBIAS);
    float*    wtot  = (float*)(dsm + SM_WTOT);
    uint32_t* wstb  = (uint32_t*)(dsm + SM_WS);   // [64][40] bf16x2 k-pairs
    float*    xs    = (float*)(dsm + SM_XS);      // [2][16][268]
    float*    zs    = (float*)(dsm + SM_XS);      // [32][260] alias (epilogue)

    const int tid  = threadIdx.x;
    const int w    = tid >> 5;
    const int lane = tid & 31;
    const int g    = lane >> 2;     // group id 0..7
    const int t    = lane & 3;      // thread-in-group 0..3

    const int pixbase = blockIdx.x * 256;
    const int b  = pixbase >> 16;
    const int ij = pixbase & 65535;

    if (tid < 32) {
        float inv = g1[tid] * rsqrtf(v1[tid] + 1e-5f);
        sinv[tid]  = inv;
        sbias[tid] = b1[tid] - m1[tid]*inv;
    }
    __syncthreads();

    // stage B = w1 * inv as bf16x2 pairs along k: wstb[c2][ch] = {w[2c2+1],w[2c2]}
    for (int idx = tid; idx < 64*BTC; idx += 256) {
        int c2 = idx >> 5;
        int ch = idx & 31;
        float inv = sinv[ch];
        wstb[c2*40 + ch] = packbf(w1[ch*CC + 2*c2 + 1] * inv,
                                  w1[ch*CC + 2*c2]     * inv);
    }
    __syncthreads();

    float acc[2][4][4];
    #pragma unroll
    for (int mt = 0; mt < 2; mt++)
        #pragma unroll
        for (int nt = 0; nt < 4; nt++)
            #pragma unroll
            for (int e = 0; e < 4; e++) acc[mt][nt][e] = 0.f;

    const int cl = tid >> 6;          // staging channel lane 0..3
    const int p4 = (tid & 63) * 4;    // staging pixel offset
    const float* xb = x + (size_t)b*CC*HWSZ + ij;
    const uint32_t xs_sb = smem_u32(xs);
    const int mypx0 = w*32 + g;       // fragment pixel base (mt adds 16)

    // prefetch chunk 0 into buf 0
    #pragma unroll
    for (int it = 0; it < 4; it++) {
        int c = it*4 + cl;            // local channel 0..15
        cp16(xs_sb + (uint32_t)(c*268 + p4)*4u,
             xb + (size_t)c*HWSZ + p4);
    }
    asm volatile("cp.async.commit_group;\n" ::);

    #pragma unroll
    for (int ch16 = 0; ch16 < 8; ch16++) {
        const int buf = ch16 & 1;
        if (ch16 < 7) {
            const int nb_ = ch16 + 1;
            const uint32_t bofs = (uint32_t)((nb_ & 1) * 16 * 268) * 4u;
            #pragma unroll
            for (int it = 0; it < 4; it++) {
                int c = it*4 + cl;
                cp16(xs_sb + bofs + (uint32_t)(c*268 + p4)*4u,
                     xb + (size_t)(nb_*16 + c)*HWSZ + p4);
            }
            asm volatile("cp.async.commit_group;\n" ::);
            asm volatile("cp.async.wait_group 1;\n" ::);
        } else {
            asm volatile("cp.async.wait_group 0;\n" ::);
        }
        __syncthreads();

        const float* xc = xs + buf*16*268;
        // ---- one k16 MMA step over this chunk ----
        uint32_t a[2][4];
        #pragma unroll
        for (int mt = 0; mt < 2; mt++) {
            const int px = mypx0 + mt*16;
            const float* r0 = xc + (2*t)*268;       // ch 2t
            const float* r1 = xc + (2*t+1)*268;     // ch 2t+1
            const float* r8 = xc + (2*t+8)*268;     // ch 2t+8
            const float* r9 = xc + (2*t+9)*268;     // ch 2t+9
            a[mt][0] = packbf(r1[px],     r0[px]);
            a[mt][1] = packbf(r1[px + 8], r0[px + 8]);
            a[mt][2] = packbf(r9[px],     r8[px]);
            a[mt][3] = packbf(r9[px + 8], r8[px + 8]);
        }
        const int kg2 = ch16*8;
        #pragma unroll
        for (int nt = 0; nt < 4; nt++) {
            uint32_t b0 = wstb[(kg2 + t)*40     + nt*8 + g];
            uint32_t b1 = wstb[(kg2 + t + 4)*40 + nt*8 + g];
            mma_bf16(acc[0][nt], a[0], b0, b1);
            mma_bf16(acc[1][nt], a[1], b0, b1);
        }
        __syncthreads();    // done reading buf before it is overwritten
    }

    // ---- scatter acc to zs[ch][260] (conflict-free, float4-aligned rows) ----
    #pragma unroll
    for (int mt = 0; mt < 2; mt++) {
        const int px = w*32 + mt*16 + g;
        #pragma unroll
        for (int nt = 0; nt < 4; nt++) {
            const int ch = nt*8 + 2*t;
            zs[ch*260 + px]           = acc[mt][nt][0];
            zs[(ch+1)*260 + px]       = acc[mt][nt][1];
            zs[ch*260 + px + 8]       = acc[mt][nt][2];
            zs[(ch+1)*260 + px + 8]   = acc[mt][nt][3];
        }
    }
    __syncthreads();

    // ---- bias + per-channel inclusive row scan (proven pattern) ----
    const int tp  = tid & 63;       // pixel group (4 px)
    const int tk  = tid >> 6;       // channel group (8 ch)
    const int wid = tid >> 5;

    float sc[4][8];
    float tot[8];
    #pragma unroll
    for (int q = 0; q < 8; q++) {
        const int ch = tk*8 + q;
        float4 v = *(float4*)&zs[ch*260 + tp*4];
        float bias = sbias[ch];
        float a0 = v.x + bias, a1 = v.y + bias, a2 = v.z + bias, a3 = v.w + bias;
        sc[0][q] = a0;
        sc[1][q] = sc[0][q] + a1;
        sc[2][q] = sc[1][q] + a2;
        sc[3][q] = sc[2][q] + a3;
        float s = sc[3][q];
        #pragma unroll
        for (int o = 1; o < 32; o <<= 1) {
            float u = __shfl_up_sync(0xffffffffu, s, o);
            if (lane >= o) s += u;
        }
        tot[q] = s;
        if (lane == 31) wtot[wid*8 + q] = s;
    }
    __syncthreads();

    #pragma unroll
    for (int q = 0; q < 8; q++) {
        const int ch = tk*8 + q;
        float off = tot[q] - sc[3][q];            // exclusive within warp
        if (wid & 1) off += wtot[(wid - 1)*8 + q];
        float4 r = make_float4(sc[0][q] + off, sc[1][q] + off,
                               sc[2][q] + off, sc[3][q] + off);
        *(float4*)(g_z + (size_t)(b*BTC + ch)*HWSZ + ij + tp*4) = r;
    }
}

// ---------------------------------------------------------------------------
// Kernel 2pre: per-chunk (32-row) column totals of row-scanned z. 1024 blocks.
// ---------------------------------------------------------------------------
__global__ __launch_bounds__(256) void k2pre_chunktot()
{
    const int chunk = blockIdx.x;            // 0..7
    const int plane = blockIdx.y;            // 0..127
    const int j     = threadIdx.x;
    const float* zp = g_z + (size_t)plane*HWSZ + (size_t)(chunk*32)*WW + j;

    float acc = 0.f;
    #pragma unroll 8
    for (int r = 0; r < 32; r++)
        acc += zp[(size_t)r*WW];
    g_ctot[plane][chunk][j] = acc;
}

// ---------------------------------------------------------------------------
// Kernel 2a: 32-row chunk column cumsum seeded with earlier-chunk prefix -> S.
// ---------------------------------------------------------------------------
__global__ __launch_bounds__(256) void k2a_colsum_chunk()
{
    const int chunk = blockIdx.x;            // 0..7
    const int plane = blockIdx.y;            // 0..127
    const int j     = threadIdx.x;
    const int r0    = chunk * 32;

    const float* zp = g_z + (size_t)plane*HWSZ + (size_t)r0*WW + j;
    float* Sp = g_S + (size_t)plane*SW*SW;

    if (chunk == 0) {
        Sp[j] = 0.f;
        if (j == 0) Sp[256] = 0.f;
    }
    if (j < 32)
        Sp[(size_t)(r0 + j + 1)*SW] = 0.f;

    float acc = 0.f;
    for (int p = 0; p < chunk; p++)
        acc += g_ctot[plane][p][j];

    #pragma unroll 8
    for (int r = 0; r < 32; r++) {
        acc += zp[(size_t)r*WW];
        Sp[(size_t)(r0 + r + 1)*SW + (j + 1)] = acc;
    }
}

// ---------------------------------------------------------------------------
// Kernel 3: separable box filter, 8-row chunks (round-13 known-good),
// with boundary row carried between the two 4-row halves (20 -> 18 S loads).
// ---------------------------------------------------------------------------
__global__ __launch_bounds__(256) void k3_box(
    const float* __restrict__ x,
    const float* __restrict__ xmn_, const float* __restrict__ xmx_,
    const float* __restrict__ ymn_, const float* __restrict__ ymx_,
    const float* __restrict__ g2, const float* __restrict__ b2,
    const float* __restrict__ m2, const float* __restrict__ v2,
    float* __restrict__ out)
{
    __shared__ float Dv[8][SW];

    const int bid = blockIdx.x;
    const int rc  = bid & 31;
    const int nb  = (bid >> 5) & (NBOX-1);
    const int bt  = (bid >> 7) & (BTC-1);
    const int b   = bid >> 12;
    const int j   = threadIdx.x;
    const int k   = bt*NBOX + nb;
    const int boxi = bt*NBOX + nb;

    const float xmn = xmn_[boxi], xmx = xmx_[boxi];
    const float ymn = ymn_[boxi], ymx = ymx_[boxi];
    const float inv_area = 1.f / ((xmx - xmn) * (ymx - ymn));

    const float* Sp = g_S + (size_t)(b*BTC + bt)*SW*SW;

    const int i0 = rc*8;
    const float aA = (float)i0 + xmx;
    const float aB = (float)i0 + xmn;
    const float fAf = floorf(aA), fBf = floorf(aB);
    const int   rA0 = (int)fAf,  rB0 = (int)fBf;
    const float wA = aA - fAf,   wB = aB - fBf;

    {
        float SA[5], SB[5];
        #pragma unroll
        for (int tt = 0; tt < 5; tt++) {
            int ra = rA0 + tt;  ra = (ra > 256) ? 256 : ra;
            int rb = rB0 + tt;  rb = (rb > 256) ? 256 : rb;
            SA[tt] = (ra < 0) ? 0.f : Sp[(size_t)ra*SW + j];
            SB[tt] = (rb < 0) ? 0.f : Sp[(size_t)rb*SW + j];
        }
        #pragma unroll
        for (int tt = 0; tt < 4; tt++)
            Dv[tt][j] = (SA[tt]*(1.f-wA) + SA[tt+1]*wA)
                      - (SB[tt]*(1.f-wB) + SB[tt+1]*wB);
        // roll boundary row into second half (save 2 loads)
        SA[0] = SA[4];  SB[0] = SB[4];
        #pragma unroll
        for (int tt = 1; tt < 5; tt++) {
            int ra = rA0 + 4 + tt;  ra = (ra > 256) ? 256 : ra;
            int rb = rB0 + 4 + tt;  rb = (rb > 256) ? 256 : rb;
            SA[tt] = (ra < 0) ? 0.f : Sp[(size_t)ra*SW + j];
            SB[tt] = (rb < 0) ? 0.f : Sp[(size_t)rb*SW + j];
        }
        #pragma unroll
        for (int tt = 0; tt < 4; tt++)
            Dv[4 + tt][j] = (SA[tt]*(1.f-wA) + SA[tt+1]*wA)
                          - (SB[tt]*(1.f-wB) + SB[tt+1]*wB);
    }
    if (j == 255) {   // column 256
        float TA[5], TB[5];
        #pragma unroll
        for (int tt = 0; tt < 5; tt++) {
            int ra = rA0 + tt;  ra = (ra > 256) ? 256 : ra;
            int rb = rB0 + tt;  rb = (rb > 256) ? 256 : rb;
            TA[tt] = (ra < 0) ? 0.f : Sp[(size_t)ra*SW + 256];
            TB[tt] = (rb < 0) ? 0.f : Sp[(size_t)rb*SW + 256];
        }
        #pragma unroll
        for (int tt = 0; tt < 4; tt++)
            Dv[tt][256] = (TA[tt]*(1.f-wA) + TA[tt+1]*wA)
                        - (TB[tt]*(1.f-wB) + TB[tt+1]*wB);
        TA[0] = TA[4];  TB[0] = TB[4];
        #pragma unroll
        for (int tt = 1; tt < 5; tt++) {
            int ra = rA0 + 4 + tt;  ra = (ra > 256) ? 256 : ra;
            int rb = rB0 + 4 + tt;  rb = (rb > 256) ? 256 : rb;
            TA[tt] = (ra < 0) ? 0.f : Sp[(size_t)ra*SW + 256];
            TB[tt] = (rb < 0) ? 0.f : Sp[(size_t)rb*SW + 256];
        }
        #pragma unroll
        for (int tt = 0; tt < 4; tt++)
            Dv[4 + tt][256] = (TA[tt]*(1.f-wA) + TA[tt+1]*wA)
                            - (TB[tt]*(1.f-wB) + TB[tt+1]*wB);
    }
    __syncthreads();

    // ---- phase 2: horizontal fractional box from smem ----
    float vA = fminf(fmaxf((float)j + ymx, 0.f), 256.f);
    float vB = fminf(fmaxf((float)j + ymn, 0.f), 256.f);
    float gA = fminf(floorf(vA), 255.f);
    float gB = fminf(floorf(vB), 255.f);
    int   jA = (int)gA, jB = (int)gB;
    float wvA = vA - gA, wvB = vB - gB;

    float inv2  = g2[k] * rsqrtf(v2[k] + 1e-3f);
    float bias2 = b2[k] - m2[k]*inv2;
    float c1    = inv_area * inv2;            // fold /area into BN2 scale

    const float* xrow = x   + ((size_t)(b*CC + k)*HH + i0)*WW + j;
    float*       orow = out + ((size_t)(b*CC + k)*HH + i0)*WW + j;

    #pragma unroll
    for (int r = 0; r < 8; r++) {
        float DA = Dv[r][jA]*(1.f - wvA) + Dv[r][jA+1]*wvA;
        float DB = Dv[r][jB]*(1.f - wvB) + Dv[r][jB+1]*wvB;
        float val = (DA - DB) * c1 + bias2;

        val = fmaxf(val, 0.f);
        orow[(size_t)r*WW] = fmaxf(xrow[(size_t)r*WW] + val, 0.f);
    }
}

// ---------------------------------------------------------------------------
extern "C" void kernel_launch(void* const* d_in, const int* in_sizes, int n_in,
                              void* d_out, int out_size)
{
    const float* x    = (const float*)d_in[0];
    const float* w1   = (const float*)d_in[1];
    const float* g1   = (const float*)d_in[2];
    const float* b1   = (const float*)d_in[3];
    const float* m1   = (const float*)d_in[4];
    const float* v1   = (const float*)d_in[5];
    const float* xmn  = (const float*)d_in[6];
    const float* xmx  = (const float*)d_in[7];
    const float* ymn  = (const float*)d_in[8];
    const float* ymx  = (const float*)d_in[9];
    const float* g2   = (const float*)d_in[10];
    const float* b2   = (const float*)d_in[11];
    const float* m2   = (const float*)d_in[12];
    const float* v2   = (const float*)d_in[13];
    float* out = (float*)d_out;

    cudaFuncSetAttribute(k1_mma_rowscan,
                         cudaFuncAttributeMaxDynamicSharedMemorySize, SM_TOTAL);

    k1_mma_rowscan<<<(BB*HWSZ)/256, 256, SM_TOTAL>>>(x, w1, g1, b1, m1, v1);
    k2pre_chunktot<<<dim3(8, BB*BTC), 256>>>();
    k2a_colsum_chunk<<<dim3(8, BB*BTC), 256>>>();
    k3_box<<<BB*BTC*NBOX*(HH/8), 256>>>(x, xmn, xmx, ymn, ymx, g2, b2, m2, v2, out);
}

// round 16
// speedup vs baseline: 1.4873x; 1.0632x over previous
#include <cuda_runtime.h>
#include <math.h>
#include <stdint.h>

#define BB 4
#define CC 128
#define NBOX 4
#define BTC 32
#define HH 256
#define WW 256
#define HWSZ (HH*WW)
#define SW 257                      // integral image row stride

// scratch (static device globals; no dynamic allocation)
__device__ float g_z[BB*BTC*HH*WW];       // ROW-SCANNED z = rowcumsum(BN1(conv))
__device__ float g_S[BB*BTC*SW*SW];       // 2D integral image, zero borders
__device__ float g_ctot[BB*BTC][8][WW];   // per-chunk (32-row) column totals

__device__ __forceinline__ uint32_t packbf(float hi, float lo) {
    uint32_t r;
    asm("cvt.rn.bf16x2.f32 %0, %1, %2;" : "=r"(r) : "f"(hi), "f"(lo));
    return r;
}
__device__ __forceinline__ void mma_bf16(float d[4], const uint32_t a[4],
                                         uint32_t b0, uint32_t b1) {
    asm volatile(
        "mma.sync.aligned.m16n8k16.row.col.f32.bf16.bf16.f32 "
        "{%0,%1,%2,%3}, {%4,%5,%6,%7}, {%8,%9}, {%0,%1,%2,%3};\n"
        : "+f"(d[0]), "+f"(d[1]), "+f"(d[2]), "+f"(d[3])
        : "r"(a[0]), "r"(a[1]), "r"(a[2]), "r"(a[3]), "r"(b0), "r"(b1));
}
__device__ __forceinline__ uint32_t smem_u32(const void* p) {
    uint32_t a;
    asm("{ .reg .u64 t; cvta.to.shared.u64 t, %1; cvt.u32.u64 %0, t; }"
        : "=r"(a) : "l"(p));
    return a;
}
__device__ __forceinline__ void cp16(uint32_t dst, const float* src) {
    asm volatile("cp.async.ca.shared.global [%0], [%1], 16;\n"
                 :: "r"(dst), "l"(src));
}

// dynamic smem layout for k1 (bytes)
#define SM_SINV  0         // 32 f
#define SM_SBIAS 128       // 32 f
#define SM_WTOT  256       // [8][8] f
#define SM_WS    512       // wstb[64][40] u32 bf16x2 weight pairs (10240 B)
#define SM_XS    10752     // xs[2][16][268] f (34304 B); zs[32][260] aliases it
#define SM_TOTAL 45056

// ---------------------------------------------------------------------------
// Kernel 1: z = rowcumsum( BN1(x @ w1^T) ) via mma.sync bf16 m16n8k16,
// cp.async double-buffered 16-channel chunks (known-good from round 13).
// ---------------------------------------------------------------------------
__global__ __launch_bounds__(256) void k1_mma_rowscan(
    const float* __restrict__ x, const float* __restrict__ w1,
    const float* __restrict__ g1, const float* __restrict__ b1,
    const float* __restrict__ m1, const float* __restrict__ v1)
{
    extern __shared__ char dsm[];
    float*    sinv  = (float*)(dsm + SM_SINV);
    float*    sbias = (float*)(dsm + SM_SBIAS);
    float*    wtot  = (float*)(dsm + SM_WTOT);
    uint32_t* wstb  = (uint32_t*)(dsm + SM_WS);   // [64][40] bf16x2 k-pairs
    float*    xs    = (float*)(dsm + SM_XS);      // [2][16][268]
    float*    zs    = (float*)(dsm + SM_XS);      // [32][260] alias (epilogue)

    const int tid  = threadIdx.x;
    const int w    = tid >> 5;
    const int lane = tid & 31;
    const int g    = lane >> 2;     // group id 0..7
    const int t    = lane & 3;      // thread-in-group 0..3

    const int pixbase = blockIdx.x * 256;
    const int b  = pixbase >> 16;
    const int ij = pixbase & 65535;

    if (tid < 32) {
        float inv = g1[tid] * rsqrtf(v1[tid] + 1e-5f);
        sinv[tid]  = inv;
        sbias[tid] = b1[tid] - m1[tid]*inv;
    }
    __syncthreads();

    // stage B = w1 * inv as bf16x2 pairs along k: wstb[c2][ch] = {w[2c2+1],w[2c2]}
    for (int idx = tid; idx < 64*BTC; idx += 256) {
        int c2 = idx >> 5;
        int ch = idx & 31;
        float inv = sinv[ch];
        wstb[c2*40 + ch] = packbf(w1[ch*CC + 2*c2 + 1] * inv,
                                  w1[ch*CC + 2*c2]     * inv);
    }
    __syncthreads();

    float acc[2][4][4];
    #pragma unroll
    for (int mt = 0; mt < 2; mt++)
        #pragma unroll
        for (int nt = 0; nt < 4; nt++)
            #pragma unroll
            for (int e = 0; e < 4; e++) acc[mt][nt][e] = 0.f;

    const int cl = tid >> 6;          // staging channel lane 0..3
    const int p4 = (tid & 63) * 4;    // staging pixel offset
    const float* xb = x + (size_t)b*CC*HWSZ + ij;
    const uint32_t xs_sb = smem_u32(xs);
    const int mypx0 = w*32 + g;       // fragment pixel base (mt adds 16)

    // prefetch chunk 0 into buf 0
    #pragma unroll
    for (int it = 0; it < 4; it++) {
        int c = it*4 + cl;            // local channel 0..15
        cp16(xs_sb + (uint32_t)(c*268 + p4)*4u,
             xb + (size_t)c*HWSZ + p4);
    }
    asm volatile("cp.async.commit_group;\n" ::);

    #pragma unroll
    for (int ch16 = 0; ch16 < 8; ch16++) {
        const int buf = ch16 & 1;
        if (ch16 < 7) {
            const int nb_ = ch16 + 1;
            const uint32_t bofs = (uint32_t)((nb_ & 1) * 16 * 268) * 4u;
            #pragma unroll
            for (int it = 0; it < 4; it++) {
                int c = it*4 + cl;
                cp16(xs_sb + bofs + (uint32_t)(c*268 + p4)*4u,
                     xb + (size_t)(nb_*16 + c)*HWSZ + p4);
            }
            asm volatile("cp.async.commit_group;\n" ::);
            asm volatile("cp.async.wait_group 1;\n" ::);
        } else {
            asm volatile("cp.async.wait_group 0;\n" ::);
        }
        __syncthreads();

        const float* xc = xs + buf*16*268;
        // ---- one k16 MMA step over this chunk ----
        uint32_t a[2][4];
        #pragma unroll
        for (int mt = 0; mt < 2; mt++) {
            const int px = mypx0 + mt*16;
            const float* r0 = xc + (2*t)*268;       // ch 2t
            const float* r1 = xc + (2*t+1)*268;     // ch 2t+1
            const float* r8 = xc + (2*t+8)*268;     // ch 2t+8
            const float* r9 = xc + (2*t+9)*268;     // ch 2t+9
            a[mt][0] = packbf(r1[px],     r0[px]);
            a[mt][1] = packbf(r1[px + 8], r0[px + 8]);
            a[mt][2] = packbf(r9[px],     r8[px]);
            a[mt][3] = packbf(r9[px + 8], r8[px + 8]);
        }
        const int kg2 = ch16*8;
        #pragma unroll
        for (int nt = 0; nt < 4; nt++) {
            uint32_t b0 = wstb[(kg2 + t)*40     + nt*8 + g];
            uint32_t b1 = wstb[(kg2 + t + 4)*40 + nt*8 + g];
            mma_bf16(acc[0][nt], a[0], b0, b1);
            mma_bf16(acc[1][nt], a[1], b0, b1);
        }
        __syncthreads();    // done reading buf before it is overwritten
    }

    // ---- scatter acc to zs[ch][260] (conflict-free, float4-aligned rows) ----
    #pragma unroll
    for (int mt = 0; mt < 2; mt++) {
        const int px = w*32 + mt*16 + g;
        #pragma unroll
        for (int nt = 0; nt < 4; nt++) {
            const int ch = nt*8 + 2*t;
            zs[ch*260 + px]           = acc[mt][nt][0];
            zs[(ch+1)*260 + px]       = acc[mt][nt][1];
            zs[ch*260 + px + 8]       = acc[mt][nt][2];
            zs[(ch+1)*260 + px + 8]   = acc[mt][nt][3];
        }
    }
    __syncthreads();

    // ---- bias + per-channel inclusive row scan (proven pattern) ----
    const int tp  = tid & 63;       // pixel group (4 px)
    const int tk  = tid >> 6;       // channel group (8 ch)
    const int wid = tid >> 5;

    float sc[4][8];
    float tot[8];
    #pragma unroll
    for (int q = 0; q < 8; q++) {
        const int ch = tk*8 + q;
        float4 v = *(float4*)&zs[ch*260 + tp*4];
        float bias = sbias[ch];
        float a0 = v.x + bias, a1 = v.y + bias, a2 = v.z + bias, a3 = v.w + bias;
        sc[0][q] = a0;
        sc[1][q] = sc[0][q] + a1;
        sc[2][q] = sc[1][q] + a2;
        sc[3][q] = sc[2][q] + a3;
        float s = sc[3][q];
        #pragma unroll
        for (int o = 1; o < 32; o <<= 1) {
            float u = __shfl_up_sync(0xffffffffu, s, o);
            if (lane >= o) s += u;
        }
        tot[q] = s;
        if (lane == 31) wtot[wid*8 + q] = s;
    }
    __syncthreads();

    #pragma unroll
    for (int q = 0; q < 8; q++) {
        const int ch = tk*8 + q;
        float off = tot[q] - sc[3][q];            // exclusive within warp
        if (wid & 1) off += wtot[(wid - 1)*8 + q];
        float4 r = make_float4(sc[0][q] + off, sc[1][q] + off,
                               sc[2][q] + off, sc[3][q] + off);
        *(float4*)(g_z + (size_t)(b*BTC + ch)*HWSZ + ij + tp*4) = r;
    }
}

// ---------------------------------------------------------------------------
// Kernel 2pre: per-chunk (32-row) column totals of row-scanned z. 1024 blocks.
// ---------------------------------------------------------------------------
__global__ __launch_bounds__(256) void k2pre_chunktot()
{
    const int chunk = blockIdx.x;            // 0..7
    const int plane = blockIdx.y;            // 0..127
    const int j     = threadIdx.x;
    const float* zp = g_z + (size_t)plane*HWSZ + (size_t)(chunk*32)*WW + j;

    float acc = 0.f;
    #pragma unroll 8
    for (int r = 0; r < 32; r++)
        acc += zp[(size_t)r*WW];
    g_ctot[plane][chunk][j] = acc;
}

// ---------------------------------------------------------------------------
// Kernel 2a: 32-row chunk column cumsum seeded with earlier-chunk prefix -> S.
// ---------------------------------------------------------------------------
__global__ __launch_bounds__(256) void k2a_colsum_chunk()
{
    const int chunk = blockIdx.x;            // 0..7
    const int plane = blockIdx.y;            // 0..127
    const int j     = threadIdx.x;
    const int r0    = chunk * 32;

    const float* zp = g_z + (size_t)plane*HWSZ + (size_t)r0*WW + j;
    float* Sp = g_S + (size_t)plane*SW*SW;

    if (chunk == 0) {
        Sp[j] = 0.f;
        if (j == 0) Sp[256] = 0.f;
    }
    if (j < 32)
        Sp[(size_t)(r0 + j + 1)*SW] = 0.f;

    float acc = 0.f;
    for (int p = 0; p < chunk; p++)
        acc += g_ctot[plane][p][j];

    #pragma unroll 8
    for (int r = 0; r < 32; r++) {
        acc += zp[(size_t)r*WW];
        Sp[(size_t)(r0 + r + 1)*SW + (j + 1)] = acc;
    }
}

// ---------------------------------------------------------------------------
// Kernel 3: separable box filter, round-13 exact version (8-row chunks,
// two independent 5+5 tap halves, inv_area folded). Measured 68.96us.
// ---------------------------------------------------------------------------
__global__ __launch_bounds__(256) void k3_box(
    const float* __restrict__ x,
    const float* __restrict__ xmn_, const float* __restrict__ xmx_,
    const float* __restrict__ ymn_, const float* __restrict__ ymx_,
    const float* __restrict__ g2, const float* __restrict__ b2,
    const float* __restrict__ m2, const float* __restrict__ v2,
    float* __restrict__ out)
{
    __shared__ float Dv[8][SW];

    const int bid = blockIdx.x;
    const int rc  = bid & 31;
    const int nb  = (bid >> 5) & (NBOX-1);
    const int bt  = (bid >> 7) & (BTC-1);
    const int b   = bid >> 12;
    const int j   = threadIdx.x;
    const int k   = bt*NBOX + nb;
    const int boxi = bt*NBOX + nb;

    const float xmn = xmn_[boxi], xmx = xmx_[boxi];
    const float ymn = ymn_[boxi], ymx = ymx_[boxi];
    const float inv_area = 1.f / ((xmx - xmn) * (ymx - ymn));

    const float* Sp = g_S + (size_t)(b*BTC + bt)*SW*SW;

    const int i0 = rc*8;
    const float aA = (float)i0 + xmx;
    const float aB = (float)i0 + xmn;
    const float fAf = floorf(aA), fBf = floorf(aB);
    const int   rA0 = (int)fAf,  rB0 = (int)fBf;
    const float wA = aA - fAf,   wB = aB - fBf;

    #pragma unroll
    for (int half = 0; half < 2; half++) {
        int rh = half*4;
        float SA[5], SB[5];
        #pragma unroll
        for (int tt = 0; tt < 5; tt++) {
            int ra = rA0 + rh + tt;  ra = (ra > 256) ? 256 : ra;
            int rb = rB0 + rh + tt;  rb = (rb > 256) ? 256 : rb;
            SA[tt] = (ra < 0) ? 0.f : Sp[(size_t)ra*SW + j];
            SB[tt] = (rb < 0) ? 0.f : Sp[(size_t)rb*SW + j];
        }
        #pragma unroll
        for (int tt = 0; tt < 4; tt++)
            Dv[rh + tt][j] = (SA[tt]*(1.f-wA) + SA[tt+1]*wA)
                           - (SB[tt]*(1.f-wB) + SB[tt+1]*wB);
        if (j == 255) {
            float TA[5], TB[5];
            #pragma unroll
            for (int tt = 0; tt < 5; tt++) {
                int ra = rA0 + rh + tt;  ra = (ra > 256) ? 256 : ra;
                int rb = rB0 + rh + tt;  rb = (rb > 256) ? 256 : rb;
                TA[tt] = (ra < 0) ? 0.f : Sp[(size_t)ra*SW + 256];
                TB[tt] = (rb < 0) ? 0.f : Sp[(size_t)rb*SW + 256];
            }
            #pragma unroll
            for (int tt = 0; tt < 4; tt++)
                Dv[rh + tt][256] = (TA[tt]*(1.f-wA) + TA[tt+1]*wA)
                                 - (TB[tt]*(1.f-wB) + TB[tt+1]*wB);
        }
    }
    __syncthreads();

    float vA = fminf(fmaxf((float)j + ymx, 0.f), 256.f);
    float vB = fminf(fmaxf((float)j + ymn, 0.f), 256.f);
    float gA = fminf(floorf(vA), 255.f);
    float gB = fminf(floorf(vB), 255.f);
    int   jA = (int)gA, jB = (int)gB;
    float wvA = vA - gA, wvB = vB - gB;

    float inv2  = g2[k] * rsqrtf(v2[k] + 1e-3f);
    float bias2 = b2[k] - m2[k]*inv2;
    float c1    = inv_area * inv2;            // fold /area into BN2 scale

    const float* xrow = x   + ((size_t)(b*CC + k)*HH + i0)*WW + j;
    float*       orow = out + ((size_t)(b*CC + k)*HH + i0)*WW + j;

    #pragma unroll
    for (int r = 0; r < 8; r++) {
        float DA = Dv[r][jA]*(1.f - wvA) + Dv[r][jA+1]*wvA;
        float DB = Dv[r][jB]*(1.f - wvB) + Dv[r][jB+1]*wvB;
        float val = (DA - DB) * c1 + bias2;

        val = fmaxf(val, 0.f);
        orow[(size_t)r*WW] = fmaxf(xrow[(size_t)r*WW] + val, 0.f);
    }
}

// ---------------------------------------------------------------------------
extern "C" void kernel_launch(void* const* d_in, const int* in_sizes, int n_in,
                              void* d_out, int out_size)
{
    const float* x    = (const float*)d_in[0];
    const float* w1   = (const float*)d_in[1];
    const float* g1   = (const float*)d_in[2];
    const float* b1   = (const float*)d_in[3];
    const float* m1   = (const float*)d_in[4];
    const float* v1   = (const float*)d_in[5];
    const float* xmn  = (const float*)d_in[6];
    const float* xmx  = (const float*)d_in[7];
    const float* ymn  = (const float*)d_in[8];
    const float* ymx  = (const float*)d_in[9];
    const float* g2   = (const float*)d_in[10];
    const float* b2   = (const float*)d_in[11];
    const float* m2   = (const float*)d_in[12];
    const float* v2   = (const float*)d_in[13];
    float* out = (float*)d_out;

    cudaFuncSetAttribute(k1_mma_rowscan,
                         cudaFuncAttributeMaxDynamicSharedMemorySize, SM_TOTAL);

    k1_mma_rowscan<<<(BB*HWSZ)/256, 256, SM_TOTAL>>>(x, w1, g1, b1, m1, v1);
    k2pre_chunktot<<<dim3(8, BB*BTC), 256>>>();
    k2a_colsum_chunk<<<dim3(8, BB*BTC), 256>>>();
    k3_box<<<BB*BTC*NBOX*(HH/8), 256>>>(x, xmn, xmx, ymn, ymx, g2, b2, m2, v2, out);
}